// round 16
// baseline (speedup 1.0000x reference)
#include <cuda_runtime.h>
#include <cstdint>
#include <math.h>

// Problem constants
constexpr int NN = 325;           // nodes
constexpr int BBATCH = 64;        // batch
constexpr int DD = 64;            // hidden units
constexpr int PP = 12;            // encoder steps
constexpr int QQ = 12;            // decoder steps
constexpr int TT = 24;            // total steps
constexpr int MROW = NN * BBATCH; // 20800 rows, layout row = n*B + b
constexpr int MTILES = (MROW + 127) / 128; // 163

// fused-kernel smem layout (bytes)
constexpr int SM_A1S   = 128 * 132 * 4;          // 67584: gathered [S0v|S1v] tf32
constexpr int SM_AS    = 128 * 36 * 4;           // 18432: A0 chunk
constexpr int SM_WS128 = 128 * 36 * 4;           // 18432
constexpr int SM_WS64  = 64 * 36 * 4;            //  9216
constexpr int SMEM_M2  = SM_A1S + SM_AS + SM_WS128; // 104448
constexpr int SMEM_M3  = SM_A1S + SM_AS + SM_WS64;  //  95232

// ---------------- device scratch (static, no allocation) ----------------
__device__ float g_vals[2 * NN * NN];
__device__ int   g_cols[2 * NN * NN];
__device__ int   g_cnt[2 * NN];
__device__ float g_te[BBATCH * TT * DD];                 // te embeddings (b,t,d)
__device__ float g_XE[(size_t)TT * MROW * DD];           // x inputs per step
__device__ float g_SX[(size_t)TT * MROW * 2 * DD];       // [S0x | S1x]
__device__ float g_Gx[(size_t)TT * MROW * 2 * DD];       // x-contribution to gate preact (+bg)
__device__ float g_Cx[(size_t)TT * MROW * DD];           // x-contribution to cand preact (+bc)
__device__ float g_h [(size_t)MROW * DD];
__device__ float g_rh[(size_t)MROW * DD];
__device__ float g_RU[(size_t)MROW * 2 * DD];            // [r | u] after sigmoid

// ---------------- helpers -------------------------------------------------
__device__ __forceinline__ uint32_t to_tf32(float x) {
    uint32_t u;
    asm("cvt.rna.tf32.f32 %0, %1;" : "=r"(u) : "f"(x));
    return u;
}

__device__ __forceinline__ void mma_tf32(float c[4], const uint32_t a[4], const uint32_t b[2]) {
    asm volatile(
        "mma.sync.aligned.m16n8k8.row.col.f32.tf32.tf32.f32 "
        "{%0,%1,%2,%3}, {%4,%5,%6,%7}, {%8,%9}, {%0,%1,%2,%3};"
        : "+f"(c[0]), "+f"(c[1]), "+f"(c[2]), "+f"(c[3])
        : "r"(a[0]), "r"(a[1]), "r"(a[2]), "r"(a[3]), "r"(b[0]), "r"(b[1]));
}

// ---------------- CSR build (deterministic ballot compaction) -----------
__global__ void build_csr_kernel(const float* __restrict__ S0,
                                 const float* __restrict__ S1) {
    int m = blockIdx.x, sup = blockIdx.y;
    const float* S = sup ? S1 : S0;
    int lane = threadIdx.x;            // blockDim = 32
    int base = (sup * NN + m) * NN;
    int cnt = 0;
    for (int start = 0; start < NN; start += 32) {
        int n = start + lane;
        float v = (n < NN) ? S[m * NN + n] : 0.f;
        unsigned mask = __ballot_sync(0xffffffffu, v != 0.f);
        if (v != 0.f) {
            int pos = cnt + __popc(mask & ((1u << lane) - 1u));
            g_cols[base + pos] = n;
            g_vals[base + pos] = v;
        }
        cnt += __popc(mask);
    }
    if (lane == 0) g_cnt[sup * NN + m] = cnt;
}

// ---------------- temporal embedding -------------------------------------
__global__ void te_kernel(const int* __restrict__ TE,
                          const float* __restrict__ W1, const float* __restrict__ b1,
                          const float* __restrict__ W2, const float* __restrict__ b2) {
    int bt = blockIdx.x;     // b*24 + t
    int d = threadIdx.x;     // 64 threads
    __shared__ float sh[DD];
    int wd = TE[bt * 2 + 0];
    int td = TE[bt * 2 + 1];
    float v = W1[wd * DD + d] + W1[(7 + td) * DD + d] + b1[d];
    sh[d] = fmaxf(v, 0.f);
    __syncthreads();
    float acc = b2[d];
#pragma unroll
    for (int k = 0; k < DD; k++) acc += sh[k] * W2[k * DD + d];
    g_te[bt * DD + d] = acc;
}

// ---------------- XE build: embX + te + E_se (enc), te + E_se (dec) ------
__global__ void xe_kernel(const float* __restrict__ X,
                          const float* __restrict__ Win1, const float* __restrict__ bin1,
                          const float* __restrict__ Win2, const float* __restrict__ bin2,
                          const float* __restrict__ Ese) {
    long rowg = (long)blockIdx.x * 2 + (threadIdx.x >> 6);  // 2 rows per block
    int d  = threadIdx.x & 63;
    int lr = threadIdx.x >> 6;
    int t = (int)(rowg / MROW);
    int r = (int)(rowg % MROW);
    int n = r / BBATCH, b = r % BBATCH;
    __shared__ float sh[2][DD];
    float out = 0.f;
    if (t < PP) {  // uniform per block (MROW even)
        float x = X[(size_t)(b * PP + t) * NN + n];
        sh[lr][d] = fmaxf(x * Win1[d] + bin1[d], 0.f);
        __syncthreads();
        float acc = bin2[d];
#pragma unroll
        for (int k = 0; k < DD; k++) acc += sh[lr][k] * Win2[k * DD + d];
        out = acc;
    }
    out += g_te[(b * TT + t) * DD + d] + Ese[n * DD + d];
    g_XE[rowg * DD + d] = out;
}

// ---------------- prologue SpMM: SX[t] = [S0 XE | S1 XE] -----------------
__global__ __launch_bounds__(256) void spmm_kernel() {
    int m = blockIdx.x;
    int t = blockIdx.y;
    int sup = blockIdx.z;
    const float* V = g_XE + (size_t)t * MROW * DD;
    float* O       = g_SX + (size_t)t * MROW * (2 * DD);

    __shared__ float sval[NN];
    __shared__ int   scol[NN];
    int cnt  = g_cnt[sup * NN + m];
    int base = (sup * NN + m) * NN;
    for (int j = threadIdx.x; j < cnt; j += 256) {
        sval[j] = g_vals[base + j];
        scol[j] = g_cols[base + j];
    }
    __syncthreads();

    int c4 = threadIdx.x & 15;   // 16 float4 groups = 64 floats
    int bq = threadIdx.x >> 4;   // 16
    float4 acc[4];
#pragma unroll
    for (int q = 0; q < 4; q++) acc[q] = make_float4(0.f, 0.f, 0.f, 0.f);

    for (int j = 0; j < cnt; j++) {
        int n = scol[j];
        float v = sval[j];
        const float* vrow = V + (size_t)n * BBATCH * DD + c4 * 4;
#pragma unroll
        for (int q = 0; q < 4; q++) {
            int b = bq + q * 16;
            float4 x = *reinterpret_cast<const float4*>(vrow + (size_t)b * DD);
            acc[q].x = fmaf(v, x.x, acc[q].x);
            acc[q].y = fmaf(v, x.y, acc[q].y);
            acc[q].z = fmaf(v, x.z, acc[q].z);
            acc[q].w = fmaf(v, x.w, acc[q].w);
        }
    }
#pragma unroll
    for (int q = 0; q < 4; q++) {
        int b = bq + q * 16;
        *reinterpret_cast<float4*>(O + ((size_t)(m * BBATCH + b)) * (2 * DD) + sup * DD + c4 * 4) = acc[q];
    }
}

// ---------------- prologue tf32 GEMMs (modes 0/1, static smem) ------------
// MODE 0: Gx = A@Wg_x + bg   (A0=XE[t], A1=SX[t]), BN=128
// MODE 1: Cx = A@Wc_x + bc   BN=64
template<int BN, int MODE>
__global__ __launch_bounds__(256, 2)
void mma_gemm_kernel(const float* __restrict__ Wenc, const float* __restrict__ Wdec,
                     const float* __restrict__ benc, const float* __restrict__ bdec) {
    constexpr int BM = 128, BK = 32, KTOT = 192;
    constexpr int NJ = (BN / 2) / 8;
    int t = blockIdx.y;
    const float* W = (t < PP) ? Wenc : Wdec;
    const float* A0 = g_XE + (size_t)t * MROW * DD;
    const float* A1 = g_SX + (size_t)t * MROW * (2 * DD);

    int mbase = blockIdx.x * BM;
    __shared__ uint32_t As[BM][36];
    __shared__ uint32_t Ws[BN][36];

    int tid  = threadIdx.x;
    int lane = tid & 31;
    int wid  = tid >> 5;
    int wm = (wid >> 1) * 32;
    int wn = (wid & 1) * (BN / 2);

    float acc[2][NJ][4];
#pragma unroll
    for (int mi = 0; mi < 2; mi++)
#pragma unroll
        for (int nj = 0; nj < NJ; nj++)
#pragma unroll
            for (int e = 0; e < 4; e++) acc[mi][nj][e] = 0.f;

    for (int ki = 0; ki < KTOT; ki += BK) {
#pragma unroll
        for (int i = 0; i < (BM * BK) / 256; i++) {
            int e  = tid + i * 256;
            int mm = e >> 5, kk = e & 31;
            int k  = ki + kk;
            int row = mbase + mm;
            float v = 0.f;
            if (row < MROW)
                v = (k < DD) ? A0[(size_t)row * DD + k]
                             : A1[(size_t)row * (2 * DD) + (k - DD)];
            As[mm][kk] = to_tf32(v);
        }
#pragma unroll
        for (int i = 0; i < (BK * BN) / 256; i++) {
            int e  = tid + i * 256;
            int nn = e % BN, kk = e / BN;
            int k  = ki + kk;
            int wrow = k + ((k >> 6) << 6);    // x-part rows
            Ws[nn][kk] = to_tf32(W[wrow * BN + nn]);
        }
        __syncthreads();
#pragma unroll
        for (int k8 = 0; k8 < BK; k8 += 8) {
            uint32_t a[2][4];
            int ar = wm + (lane >> 2);
            int ak = k8 + (lane & 3);
#pragma unroll
            for (int mi = 0; mi < 2; mi++) {
                int r = ar + mi * 16;
                a[mi][0] = As[r][ak];
                a[mi][1] = As[r + 8][ak];
                a[mi][2] = As[r][ak + 4];
                a[mi][3] = As[r + 8][ak + 4];
            }
            uint32_t b[NJ][2];
#pragma unroll
            for (int nj = 0; nj < NJ; nj++) {
                int bn = wn + nj * 8 + (lane >> 2);
                int bk = k8 + (lane & 3);
                b[nj][0] = Ws[bn][bk];
                b[nj][1] = Ws[bn][bk + 4];
            }
#pragma unroll
            for (int mi = 0; mi < 2; mi++)
#pragma unroll
                for (int nj = 0; nj < NJ; nj++)
                    mma_tf32(acc[mi][nj], a[mi], b[nj]);
        }
        __syncthreads();
    }

    const float* bias = (t < PP) ? benc : bdec;
#pragma unroll
    for (int mi = 0; mi < 2; mi++) {
        int r0 = mbase + wm + mi * 16 + (lane >> 2);
#pragma unroll
        for (int nj = 0; nj < NJ; nj++) {
            int col0 = wn + nj * 8 + 2 * (lane & 3);
#pragma unroll
            for (int e = 0; e < 4; e++) {
                int row = r0 + (e >> 1) * 8;
                int col = col0 + (e & 1);
                if (row >= MROW) continue;
                float v = acc[mi][nj][e] + bias[col];
                if (MODE == 0) g_Gx[((size_t)t * MROW + row) * 128 + col] = v;
                else           g_Cx[((size_t)t * MROW + row) * 64 + col] = v;
            }
        }
    }
}

// ---------------- fused recurrent kernel (modes 2/3) ----------------------
// Gathers its own [S0v|S1v] tile (2 nodes x 64 batch) into smem as tf32,
// then runs the tf32 MMA mainloop (K=192: A0 from gmem chunks, A1 from smem).
// MODE 2: RU = sigmoid(A@Wg_h + Gx[t]); rh = r*h        (v=h),  BN=128
// MODE 3: c = tanh(A@Wc_h + Cx[t]); h = u*h+(1-u)*c; + fused output head (v=rh), BN=64
template<int MODE>
__global__ __launch_bounds__(256, 2)
void mma_fused_kernel(const float* __restrict__ Wenc, const float* __restrict__ Wdec,
                      int t,
                      const float* __restrict__ W1o, const float* __restrict__ b1o,
                      const float* __restrict__ W2o, const float* __restrict__ b2o,
                      float* __restrict__ out) {
    constexpr int BN = (MODE == 2) ? 128 : 64;
    constexpr int NJ = (BN / 2) / 8;
    extern __shared__ unsigned char smem_raw[];
    uint32_t (*A1s)[132] = reinterpret_cast<uint32_t(*)[132]>(smem_raw);
    uint32_t (*As)[36]   = reinterpret_cast<uint32_t(*)[36]>(smem_raw + SM_A1S);
    uint32_t (*Ws)[36]   = reinterpret_cast<uint32_t(*)[36]>(smem_raw + SM_A1S + SM_AS);
    float (*h_smem)[132] = reinterpret_cast<float(*)[132]>(smem_raw);  // alias A1s (MODE 3 only)

    const float* V  = (MODE == 2) ? g_h : g_rh;   // gather + A0 source
    const float* W  = (t < PP) ? Wenc : Wdec;

    int tid = threadIdx.x;
    int bx = blockIdx.x;
    int mbase = bx * 128;

    // ---- gather phase: A1s[128][0:128] = [S0v | S1v] tf32 ----
    {
        int c4 = tid & 15, bq = tid >> 4;
        for (int p = 0; p < 4; p++) {
            int node = 2 * bx + (p >> 1);
            int sup = p & 1;
            if (node >= NN) break;
            int cnt  = g_cnt[sup * NN + node];
            int base = (sup * NN + node) * NN;
            float4 acc[4];
#pragma unroll
            for (int q = 0; q < 4; q++) acc[q] = make_float4(0.f, 0.f, 0.f, 0.f);
            for (int j = 0; j < cnt; j++) {
                int n   = __ldg(&g_cols[base + j]);
                float v = __ldg(&g_vals[base + j]);
                const float* vrow = V + (size_t)n * (BBATCH * DD) + c4 * 4;
#pragma unroll
                for (int q = 0; q < 4; q++) {
                    int b = bq + q * 16;
                    float4 x = *reinterpret_cast<const float4*>(vrow + (size_t)b * DD);
                    acc[q].x = fmaf(v, x.x, acc[q].x);
                    acc[q].y = fmaf(v, x.y, acc[q].y);
                    acc[q].z = fmaf(v, x.z, acc[q].z);
                    acc[q].w = fmaf(v, x.w, acc[q].w);
                }
            }
            int rl = (p >> 1) * 64;
            int cb = sup * 64 + c4 * 4;
#pragma unroll
            for (int q = 0; q < 4; q++) {
                int row = rl + bq + q * 16;
                A1s[row][cb + 0] = to_tf32(acc[q].x);
                A1s[row][cb + 1] = to_tf32(acc[q].y);
                A1s[row][cb + 2] = to_tf32(acc[q].z);
                A1s[row][cb + 3] = to_tf32(acc[q].w);
            }
        }
    }
    __syncthreads();

    // ---- MMA mainloop ----
    int lane = tid & 31;
    int wid  = tid >> 5;
    int wm = (wid >> 1) * 32;
    int wn = (wid & 1) * (BN / 2);

    float acc[2][NJ][4];
#pragma unroll
    for (int mi = 0; mi < 2; mi++)
#pragma unroll
        for (int nj = 0; nj < NJ; nj++)
#pragma unroll
            for (int e = 0; e < 4; e++) acc[mi][nj][e] = 0.f;

#pragma unroll
    for (int ki = 0; ki < 192; ki += 32) {
        if (ki < 64) {
#pragma unroll
            for (int i = 0; i < 16; i++) {
                int e  = tid + i * 256;
                int mm = e >> 5, kk = e & 31;
                int row = mbase + mm;
                float v = (row < MROW) ? V[(size_t)row * DD + ki + kk] : 0.f;
                As[mm][kk] = to_tf32(v);
            }
        }
#pragma unroll
        for (int i = 0; i < (32 * BN) / 256; i++) {
            int e  = tid + i * 256;
            int nn = e % BN, kk = e / BN;
            int k  = ki + kk;
            int wrow = DD + k + ((k >> 6) << 6);   // h-part rows
            Ws[nn][kk] = to_tf32(W[wrow * BN + nn]);
        }
        __syncthreads();
#pragma unroll
        for (int k8 = 0; k8 < 32; k8 += 8) {
            uint32_t a[2][4];
            int ar = wm + (lane >> 2);
#pragma unroll
            for (int mi = 0; mi < 2; mi++) {
                int r = ar + mi * 16;
                if (ki < 64) {
                    int ak = k8 + (lane & 3);
                    a[mi][0] = As[r][ak];
                    a[mi][1] = As[r + 8][ak];
                    a[mi][2] = As[r][ak + 4];
                    a[mi][3] = As[r + 8][ak + 4];
                } else {
                    int ak = (ki - 64) + k8 + (lane & 3);
                    a[mi][0] = A1s[r][ak];
                    a[mi][1] = A1s[r + 8][ak];
                    a[mi][2] = A1s[r][ak + 4];
                    a[mi][3] = A1s[r + 8][ak + 4];
                }
            }
            uint32_t b[NJ][2];
#pragma unroll
            for (int nj = 0; nj < NJ; nj++) {
                int bn = wn + nj * 8 + (lane >> 2);
                int bk = k8 + (lane & 3);
                b[nj][0] = Ws[bn][bk];
                b[nj][1] = Ws[bn][bk + 4];
            }
#pragma unroll
            for (int mi = 0; mi < 2; mi++)
#pragma unroll
                for (int nj = 0; nj < NJ; nj++)
                    mma_tf32(acc[mi][nj], a[mi], b[nj]);
        }
        __syncthreads();
    }

    // ---- epilogue ----
#pragma unroll
    for (int mi = 0; mi < 2; mi++) {
        int rl0 = wm + mi * 16 + (lane >> 2);
#pragma unroll
        for (int nj = 0; nj < NJ; nj++) {
            int col0 = wn + nj * 8 + 2 * (lane & 3);
#pragma unroll
            for (int e = 0; e < 4; e++) {
                int rl  = rl0 + (e >> 1) * 8;
                int row = mbase + rl;
                int col = col0 + (e & 1);
                if (row >= MROW) continue;
                float v = acc[mi][nj][e];
                if (MODE == 2) {
                    v += g_Gx[((size_t)t * MROW + row) * 128 + col];
                    float s = 1.f / (1.f + expf(-v));
                    g_RU[(size_t)row * 128 + col] = s;
                    if (col < DD) g_rh[(size_t)row * DD + col] = s * g_h[(size_t)row * DD + col];
                } else {
                    v += g_Cx[((size_t)t * MROW + row) * 64 + col];
                    float c = tanhf(v);
                    float u = g_RU[(size_t)row * 128 + DD + col];
                    float hold = g_h[(size_t)row * DD + col];
                    float hn = u * hold + (1.f - u) * c;
                    g_h[(size_t)row * DD + col] = hn;
                    h_smem[rl][col] = hn;
                }
            }
        }
    }

    // ---- fused output head (MODE 3, decoder steps) ----
    if (MODE == 3 && t >= PP) {
        __syncthreads();
        int row_l = tid >> 1;          // 0..127
        int half  = tid & 1;
        int row_g = mbase + row_l;
        float accd[32];
#pragma unroll
        for (int i = 0; i < 32; i++) accd[i] = b1o[32 * half + i];
#pragma unroll 8
        for (int k = 0; k < 64; k++) {
            float hk = h_smem[row_l][k];
            const float* w1r = W1o + k * 64 + 32 * half;
#pragma unroll
            for (int i = 0; i < 32; i++) accd[i] = fmaf(hk, w1r[i], accd[i]);
        }
        float part = 0.f;
#pragma unroll
        for (int i = 0; i < 32; i++) part += fmaxf(accd[i], 0.f) * W2o[32 * half + i];
        part += __shfl_xor_sync(0xffffffffu, part, 1);
        if (half == 0 && row_g < MROW) {
            int n = row_g / BBATCH, b = row_g % BBATCH;
            out[(size_t)(b * QQ + (t - PP)) * NN + n] = part + b2o[0];
        }
    }
}

__global__ void zero_h_kernel() {
    size_t i = (size_t)blockIdx.x * 256 + threadIdx.x;
    if (i < (size_t)MROW * DD) g_h[i] = 0.f;
}

// ---------------- launcher -------------------------------------------------
extern "C" void kernel_launch(void* const* d_in, const int* in_sizes, int n_in,
                              void* d_out, int out_size) {
    (void)in_sizes; (void)n_in; (void)out_size;
    const float* X      = (const float*)d_in[0];
    const int*   TE     = (const int*)  d_in[1];
    const float* S0     = (const float*)d_in[2];
    const float* S1     = (const float*)d_in[3];
    const float* W_te1  = (const float*)d_in[4];
    const float* b_te1  = (const float*)d_in[5];
    const float* W_te2  = (const float*)d_in[6];
    const float* b_te2  = (const float*)d_in[7];
    const float* E_se   = (const float*)d_in[8];
    const float* W_in1  = (const float*)d_in[9];
    const float* b_in1  = (const float*)d_in[10];
    const float* W_in2  = (const float*)d_in[11];
    const float* b_in2  = (const float*)d_in[12];
    const float* enc_Wg = (const float*)d_in[13];
    const float* enc_bg = (const float*)d_in[14];
    const float* enc_Wc = (const float*)d_in[15];
    const float* enc_bc = (const float*)d_in[16];
    const float* dec_Wg = (const float*)d_in[17];
    const float* dec_bg = (const float*)d_in[18];
    const float* dec_Wc = (const float*)d_in[19];
    const float* dec_bc = (const float*)d_in[20];
    const float* W_out1 = (const float*)d_in[21];
    const float* b_out1 = (const float*)d_in[22];
    const float* W_out2 = (const float*)d_in[23];
    const float* b_out2 = (const float*)d_in[24];
    float* out = (float*)d_out;

    cudaFuncSetAttribute(mma_fused_kernel<2>, cudaFuncAttributeMaxDynamicSharedMemorySize, SMEM_M2);
    cudaFuncSetAttribute(mma_fused_kernel<3>, cudaFuncAttributeMaxDynamicSharedMemorySize, SMEM_M3);

    // prologue
    build_csr_kernel<<<dim3(NN, 2), 32>>>(S0, S1);
    te_kernel<<<BBATCH * TT, DD>>>(TE, W_te1, b_te1, W_te2, b_te2);
    xe_kernel<<<(TT * MROW) / 2, 128>>>(X, W_in1, b_in1, W_in2, b_in2, E_se);
    spmm_kernel<<<dim3(NN, TT, 2), 256>>>();                                   // SX
    mma_gemm_kernel<128, 0><<<dim3(MTILES, TT), 256>>>(enc_Wg, dec_Wg, enc_bg, dec_bg); // Gx
    mma_gemm_kernel<64, 1><<<dim3(MTILES, TT), 256>>>(enc_Wc, dec_Wc, enc_bc, dec_bc);  // Cx
    zero_h_kernel<<<(MROW * DD) / 256, 256>>>();

    // recurrence: 2 fused launches per step
    for (int t = 0; t < TT; t++) {
        mma_fused_kernel<2><<<MTILES, 256, SMEM_M2>>>(enc_Wg, dec_Wg, t,
                                                      W_out1, b_out1, W_out2, b_out2, out);
        mma_fused_kernel<3><<<MTILES, 256, SMEM_M3>>>(enc_Wc, dec_Wc, t,
                                                      W_out1, b_out1, W_out2, b_out2, out);
    }
}